// round 4
// baseline (speedup 1.0000x reference)
#include <cuda_runtime.h>
#include <math.h>

#define BT 4096   // b*t
#define T  2048
#define E  1024
#define H  16
#define S  64

// Scratch (allocation-free rule: device globals)
__device__ float g_Q[BT * E];
__device__ float g_K[BT * E];
__device__ float g_V[BT * E];
__device__ float g_O[BT * E];

// ---------------------------------------------------------------------------
// GEMM: C[M,N] = A[M,K] * B[N,K]^T   (M=4096, N=1024, K=1024 for all 4 uses)
// Block tile 128x64, BK=16, 256 threads, 8x4 per-thread micro-tile.
// ---------------------------------------------------------------------------
__global__ __launch_bounds__(256) void gemm_nt(const float* __restrict__ A,
                                               const float* __restrict__ B,
                                               float* __restrict__ C)
{
    const int Kd = 1024, Nd = 1024;
    __shared__ float As[16][128];     // k-major
    __shared__ float Bs[16][68];      // k-major, padded (68*4B = 17 lines, 16B-aligned rows)

    const int bm = blockIdx.y * 128;
    const int bn = blockIdx.x * 64;
    const int tid = threadIdx.x;
    const int tx = tid & 15;          // col group -> cols tx*4..+3
    const int ty = tid >> 4;          // row group -> rows ty*8..+7

    float acc[8][4];
#pragma unroll
    for (int i = 0; i < 8; i++)
#pragma unroll
        for (int j = 0; j < 4; j++) acc[i][j] = 0.f;

    for (int k0 = 0; k0 < Kd; k0 += 16) {
        // Load A tile: 128 rows x 16 cols = 512 float4, 2 per thread
#pragma unroll
        for (int i = 0; i < 2; i++) {
            int idx = tid + i * 256;
            int r = idx >> 2, c4 = idx & 3;
            float4 v = *(const float4*)&A[(size_t)(bm + r) * Kd + k0 + c4 * 4];
            As[c4 * 4 + 0][r] = v.x;
            As[c4 * 4 + 1][r] = v.y;
            As[c4 * 4 + 2][r] = v.z;
            As[c4 * 4 + 3][r] = v.w;
        }
        // Load B tile: 64 rows x 16 cols = 256 float4, 1 per thread
        {
            int r = tid >> 2, c4 = tid & 3;
            float4 v = *(const float4*)&B[(size_t)(bn + r) * Kd + k0 + c4 * 4];
            Bs[c4 * 4 + 0][r] = v.x;
            Bs[c4 * 4 + 1][r] = v.y;
            Bs[c4 * 4 + 2][r] = v.z;
            Bs[c4 * 4 + 3][r] = v.w;
        }
        __syncthreads();

#pragma unroll
        for (int kk = 0; kk < 16; kk++) {
            float a[8], bb[4];
            *(float4*)&a[0] = *(const float4*)&As[kk][ty * 8];
            *(float4*)&a[4] = *(const float4*)&As[kk][ty * 8 + 4];
            *(float4*)&bb[0] = *(const float4*)&Bs[kk][tx * 4];
#pragma unroll
            for (int i = 0; i < 8; i++)
#pragma unroll
                for (int j = 0; j < 4; j++)
                    acc[i][j] += a[i] * bb[j];
        }
        __syncthreads();
    }

#pragma unroll
    for (int i = 0; i < 8; i++) {
        float4 v = make_float4(acc[i][0], acc[i][1], acc[i][2], acc[i][3]);
        *(float4*)&C[(size_t)(bm + ty * 8 + i) * Nd + bn + tx * 4] = v;
    }
}

// ---------------------------------------------------------------------------
// Per-head LayerNorm over last dim S=64, in-place. One warp per (b,t,h) vector.
// ---------------------------------------------------------------------------
__global__ __launch_bounds__(256) void ln_heads(float* __restrict__ buf,
                                                const float* __restrict__ w,
                                                const float* __restrict__ b)
{
    int gw = (blockIdx.x * blockDim.x + threadIdx.x) >> 5;
    int lane = threadIdx.x & 31;
    if (gw >= BT * H) return;

    float* v = buf + (size_t)gw * S;
    float2 x = *(float2*)&v[lane * 2];

    float sum = x.x + x.y;
#pragma unroll
    for (int o = 16; o > 0; o >>= 1) sum += __shfl_xor_sync(0xffffffffu, sum, o);
    float mu = sum * (1.0f / 64.0f);

    float dx = x.x - mu, dy = x.y - mu;
    float vs = dx * dx + dy * dy;
#pragma unroll
    for (int o = 16; o > 0; o >>= 1) vs += __shfl_xor_sync(0xffffffffu, vs, o);
    float rs = rsqrtf(vs * (1.0f / 64.0f) + 1e-5f);

    float2 o2;
    o2.x = dx * rs * w[lane * 2]     + b[lane * 2];
    o2.y = dy * rs * w[lane * 2 + 1] + b[lane * 2 + 1];
    *(float2*)&v[lane * 2] = o2;
}

// ---------------------------------------------------------------------------
// Causal flash attention, fp32. One block per (64-query tile, b*h).
// Tiles 64x64, online softmax, P staged through the Ks buffer (aliased).
// smem: Qs/Ks/Vs each [64][68] floats -> 52224 B dynamic.
// ---------------------------------------------------------------------------
#define LDA 68
__global__ __launch_bounds__(256) void attn(const float* __restrict__ Q,
                                            const float* __restrict__ K,
                                            const float* __restrict__ V,
                                            float* __restrict__ O)
{
    extern __shared__ float sm[];
    float* Qs = sm;                 // [64][LDA]
    float* Ks = sm + 64 * LDA;      // [64][LDA], reused as Ps after scores
    float* Vs = sm + 2 * 64 * LDA;  // [64][LDA]

    const int qt = gridDim.x - 1 - blockIdx.x;   // big tiles launch first
    const int bh = blockIdx.y;
    const int b  = bh >> 4, h = bh & 15;
    const int tid = threadIdx.x;
    const int tg = tid >> 4;        // 0..15 : query rows rq..rq+3
    const int tx = tid & 15;        // 0..15 : score keys {tx+16j}, output cols tx*4..+3
    const int rq = tg * 4;
    const int ck = tx * 4;

    const size_t qbase = ((size_t)b * T + (size_t)qt * 64) * E + h * S;

    // Load Q tile (coalesced 256B per 16 lanes)
    for (int idx = tid; idx < 64 * 16; idx += 256) {
        int r = idx >> 4, c4 = idx & 15;
        *(float4*)&Qs[r * LDA + c4 * 4] =
            *(const float4*)&Q[qbase + (size_t)r * E + c4 * 4];
    }

    float m[4], l[4], acc[4][4];
#pragma unroll
    for (int i = 0; i < 4; i++) {
        m[i] = -1e30f; l[i] = 0.f;
#pragma unroll
        for (int j = 0; j < 4; j++) acc[i][j] = 0.f;
    }

    for (int kt = 0; kt <= qt; kt++) {
        const size_t kbase = ((size_t)b * T + (size_t)kt * 64) * E + h * S;
        __syncthreads();   // covers Qs on iter 0; Ps/Vs reads on later iters
        for (int idx = tid; idx < 64 * 16; idx += 256) {
            int r = idx >> 4, c4 = idx & 15;
            *(float4*)&Ks[r * LDA + c4 * 4] =
                *(const float4*)&K[kbase + (size_t)r * E + c4 * 4];
            *(float4*)&Vs[r * LDA + c4 * 4] =
                *(const float4*)&V[kbase + (size_t)r * E + c4 * 4];
        }
        __syncthreads();

        // ---- scores: s[i][j] = q(rq+i) . k(tx+16j) ----
        float s[4][4];
#pragma unroll
        for (int i = 0; i < 4; i++)
#pragma unroll
            for (int j = 0; j < 4; j++) s[i][j] = 0.f;

#pragma unroll 4
        for (int k4 = 0; k4 < 64; k4 += 4) {
            float qv[4][4], kv[4][4];
#pragma unroll
            for (int i = 0; i < 4; i++)
                *(float4*)qv[i] = *(const float4*)&Qs[(rq + i) * LDA + k4];
#pragma unroll
            for (int j = 0; j < 4; j++)
                *(float4*)kv[j] = *(const float4*)&Ks[(tx + 16 * j) * LDA + k4];
#pragma unroll
            for (int i = 0; i < 4; i++)
#pragma unroll
                for (int j = 0; j < 4; j++)
#pragma unroll
                    for (int kk = 0; kk < 4; kk++)
                        s[i][j] += qv[i][kk] * kv[j][kk];
        }

        const bool diag = (kt == qt);
#pragma unroll
        for (int i = 0; i < 4; i++) {
#pragma unroll
            for (int j = 0; j < 4; j++) {
                float sv = s[i][j] * 0.125f;   // 1/sqrt(64)
                if (diag && (tx + 16 * j > rq + i)) sv = -1e30f;
                s[i][j] = sv;
            }
            // row reduce across the 16 lanes holding this query row
            float rmax = fmaxf(fmaxf(s[i][0], s[i][1]), fmaxf(s[i][2], s[i][3]));
#pragma unroll
            for (int o = 8; o > 0; o >>= 1)
                rmax = fmaxf(rmax, __shfl_xor_sync(0xffffffffu, rmax, o));
            float mnew = fmaxf(m[i], rmax);
            float rsum = 0.f;
#pragma unroll
            for (int j = 0; j < 4; j++) {
                s[i][j] = __expf(s[i][j] - mnew);
                rsum += s[i][j];
            }
#pragma unroll
            for (int o = 8; o > 0; o >>= 1)
                rsum += __shfl_xor_sync(0xffffffffu, rsum, o);
            float alpha = __expf(m[i] - mnew);
            m[i] = mnew;
            l[i] = l[i] * alpha + rsum;
#pragma unroll
            for (int j = 0; j < 4; j++) acc[i][j] *= alpha;
        }

        __syncthreads();   // everyone done reading Ks
        // stage P into the Ks buffer (Ps[row][keycol])
#pragma unroll
        for (int i = 0; i < 4; i++)
#pragma unroll
            for (int j = 0; j < 4; j++)
                Ks[(rq + i) * LDA + tx + 16 * j] = s[i][j];
        __syncthreads();

        // ---- PV: acc[i][j] += sum_c P[rq+i][c] * V[c][ck+j] ----
#pragma unroll 4
        for (int c = 0; c < 64; c += 4) {
            float vv[4][4];
#pragma unroll
            for (int cc = 0; cc < 4; cc++)
                *(float4*)vv[cc] = *(const float4*)&Vs[(c + cc) * LDA + ck];
#pragma unroll
            for (int i = 0; i < 4; i++) {
                float pr[4];
                *(float4*)pr = *(const float4*)&Ks[(rq + i) * LDA + c];
#pragma unroll
                for (int cc = 0; cc < 4; cc++)
#pragma unroll
                    for (int j = 0; j < 4; j++)
                        acc[i][j] += pr[cc] * vv[cc][j];
            }
        }
    }

#pragma unroll
    for (int i = 0; i < 4; i++) {
        float inv = 1.0f / l[i];
        float4 v = make_float4(acc[i][0] * inv, acc[i][1] * inv,
                               acc[i][2] * inv, acc[i][3] * inv);
        *(float4*)&O[qbase + (size_t)(rq + i) * E + ck] = v;
    }
}

// ---------------------------------------------------------------------------
extern "C" void kernel_launch(void* const* d_in, const int* in_sizes, int n_in,
                              void* d_out, int out_size)
{
    const float* x    = (const float*)d_in[0];
    const float* Wk   = (const float*)d_in[1];
    const float* Wq   = (const float*)d_in[2];
    const float* Wv   = (const float*)d_in[3];
    const float* Wu   = (const float*)d_in[4];
    const float* klnw = (const float*)d_in[5];
    const float* klnb = (const float*)d_in[6];
    const float* qlnw = (const float*)d_in[7];
    const float* qlnb = (const float*)d_in[8];
    float* out = (float*)d_out;

    float *gq, *gk, *gv, *go;
    cudaGetSymbolAddress((void**)&gq, g_Q);
    cudaGetSymbolAddress((void**)&gk, g_K);
    cudaGetSymbolAddress((void**)&gv, g_V);
    cudaGetSymbolAddress((void**)&go, g_O);

    const int attn_smem = 3 * 64 * LDA * (int)sizeof(float);  // 52224 B
    cudaFuncSetAttribute(attn, cudaFuncAttributeMaxDynamicSharedMemorySize, attn_smem);

    dim3 gemm_grid(16, 32);   // N/64, M/128
    gemm_nt<<<gemm_grid, 256>>>(x, Wq, gq);
    gemm_nt<<<gemm_grid, 256>>>(x, Wk, gk);
    gemm_nt<<<gemm_grid, 256>>>(x, Wv, gv);

    ln_heads<<<8192, 256>>>(gq, qlnw, qlnb);
    ln_heads<<<8192, 256>>>(gk, klnw, klnb);

    attn<<<dim3(32, 32), 256, attn_smem>>>(gq, gk, gv, go);

    gemm_nt<<<gemm_grid, 256>>>(go, Wu, out);
}

// round 6
// speedup vs baseline: 1.6379x; 1.6379x over previous
#include <cuda_runtime.h>
#include <math.h>

#define BT 4096   // b*t
#define T  2048
#define E  1024
#define H  16
#define S  64

// Scratch (allocation-free rule: device globals)
__device__ float g_Q[BT * E];
__device__ float g_K[BT * E];
__device__ float g_V[BT * E];
__device__ float g_O[BT * E];

// ---------------------------------------------------------------------------
// tf32 helpers
// ---------------------------------------------------------------------------
__device__ __forceinline__ unsigned f2tf(float f) {
    unsigned u;
    asm("cvt.rna.tf32.f32 %0, %1;" : "=r"(u) : "f"(f));
    return u;
}
__device__ __forceinline__ unsigned smem_u32(const void* p) {
    return (unsigned)__cvta_generic_to_shared(p);
}
__device__ __forceinline__ void ldsm_x4(unsigned& r0, unsigned& r1,
                                        unsigned& r2, unsigned& r3, unsigned a) {
    asm volatile("ldmatrix.sync.aligned.m8n8.x4.shared.b16 {%0,%1,%2,%3}, [%4];"
                 : "=r"(r0), "=r"(r1), "=r"(r2), "=r"(r3) : "r"(a));
}
__device__ __forceinline__ void ldsm_x2(unsigned& r0, unsigned& r1, unsigned a) {
    asm volatile("ldmatrix.sync.aligned.m8n8.x2.shared.b16 {%0,%1}, [%2];"
                 : "=r"(r0), "=r"(r1) : "r"(a));
}
__device__ __forceinline__ void mma_tf32(float* c, const unsigned* a, const unsigned* b) {
    asm volatile("mma.sync.aligned.m16n8k8.row.col.f32.tf32.tf32.f32 "
                 "{%0,%1,%2,%3}, {%4,%5,%6,%7}, {%8,%9}, {%0,%1,%2,%3};"
                 : "+f"(c[0]), "+f"(c[1]), "+f"(c[2]), "+f"(c[3])
                 : "r"(a[0]), "r"(a[1]), "r"(a[2]), "r"(a[3]),
                   "r"(b[0]), "r"(b[1]));
}

// ---------------------------------------------------------------------------
// GEMM (tf32 tensor cores): C[M,N] = A[M,K] * B[N,K]^T,  K=N=1024.
// Block 128x128, BK=16, 256 threads (8 warps, 2x4), warp tile 64x32.
// A,B staged in smem as round-to-nearest tf32; fragments via ldmatrix.
// ---------------------------------------------------------------------------
#define LDSW 20   // smem row stride in 32-bit words (80B: conflict-free LDSM)
__global__ __launch_bounds__(256) void gemm_tf32(const float* __restrict__ A,
                                                 const float* __restrict__ B,
                                                 float* __restrict__ C)
{
    __shared__ __align__(16) unsigned As[128 * LDSW];
    __shared__ __align__(16) unsigned Bs[128 * LDSW];

    const int tid  = threadIdx.x;
    const int lane = tid & 31;
    const int warp = tid >> 5;
    const int wm = (warp & 1) * 64;     // warp M offset
    const int wn = (warp >> 1) * 32;    // warp N offset
    const int bm = blockIdx.y * 128;
    const int bn = blockIdx.x * 128;

    // gmem staging assignment: rows r and r+64, 16B chunk c4
    const int r  = tid >> 2;            // 0..63
    const int c4 = tid & 3;             // 0..3

    float c[4][4][4];
#pragma unroll
    for (int mt = 0; mt < 4; mt++)
#pragma unroll
        for (int nt = 0; nt < 4; nt++)
#pragma unroll
            for (int i = 0; i < 4; i++) c[mt][nt][i] = 0.f;

    const float* Ap0 = A + (size_t)(bm + r) * 1024 + c4 * 4;
    const float* Ap1 = A + (size_t)(bm + r + 64) * 1024 + c4 * 4;
    const float* Bp0 = B + (size_t)(bn + r) * 1024 + c4 * 4;
    const float* Bp1 = B + (size_t)(bn + r + 64) * 1024 + c4 * 4;

    // LDSM base addresses (byte offsets into smem)
    const unsigned a_base = smem_u32(As) + (unsigned)((wm + (lane & 15)) * LDSW * 4
                                                      + ((lane >> 4) & 1) * 16);
    const unsigned b_base = smem_u32(Bs) + (unsigned)((wn + (lane & 7)) * LDSW * 4
                                                      + ((lane >> 3) & 1) * 16);

    float4 pa0 = *(const float4*)Ap0;
    float4 pa1 = *(const float4*)Ap1;
    float4 pb0 = *(const float4*)Bp0;
    float4 pb1 = *(const float4*)Bp1;

    for (int k0 = 0; k0 < 1024; k0 += 16) {
        // stage current tile (round to tf32)
        {
            uint4 u;
            u.x = f2tf(pa0.x); u.y = f2tf(pa0.y); u.z = f2tf(pa0.z); u.w = f2tf(pa0.w);
            *(uint4*)&As[r * LDSW + c4 * 4] = u;
            u.x = f2tf(pa1.x); u.y = f2tf(pa1.y); u.z = f2tf(pa1.z); u.w = f2tf(pa1.w);
            *(uint4*)&As[(r + 64) * LDSW + c4 * 4] = u;
            u.x = f2tf(pb0.x); u.y = f2tf(pb0.y); u.z = f2tf(pb0.z); u.w = f2tf(pb0.w);
            *(uint4*)&Bs[r * LDSW + c4 * 4] = u;
            u.x = f2tf(pb1.x); u.y = f2tf(pb1.y); u.z = f2tf(pb1.z); u.w = f2tf(pb1.w);
            *(uint4*)&Bs[(r + 64) * LDSW + c4 * 4] = u;
        }
        __syncthreads();

        // prefetch next tile into registers
        if (k0 + 16 < 1024) {
            pa0 = *(const float4*)(Ap0 + k0 + 16);
            pa1 = *(const float4*)(Ap1 + k0 + 16);
            pb0 = *(const float4*)(Bp0 + k0 + 16);
            pb1 = *(const float4*)(Bp1 + k0 + 16);
        }

        // compute: 2 k-steps of 8
#pragma unroll
        for (int ks = 0; ks < 2; ks++) {
            unsigned af[4][4], bf[4][2];
#pragma unroll
            for (int mt = 0; mt < 4; mt++)
                ldsm_x4(af[mt][0], af[mt][1], af[mt][2], af[mt][3],
                        a_base + (unsigned)(mt * 16 * LDSW * 4 + ks * 32));
#pragma unroll
            for (int nt = 0; nt < 4; nt++)
                ldsm_x2(bf[nt][0], bf[nt][1],
                        b_base + (unsigned)(nt * 8 * LDSW * 4 + ks * 32));
#pragma unroll
            for (int mt = 0; mt < 4; mt++)
#pragma unroll
                for (int nt = 0; nt < 4; nt++)
                    mma_tf32(c[mt][nt], af[mt], bf[nt]);
        }
        __syncthreads();
    }

    // epilogue
#pragma unroll
    for (int mt = 0; mt < 4; mt++) {
#pragma unroll
        for (int nt = 0; nt < 4; nt++) {
            int row = bm + wm + mt * 16 + (lane >> 2);
            int col = bn + wn + nt * 8 + (lane & 3) * 2;
            *(float2*)&C[(size_t)row * 1024 + col] =
                make_float2(c[mt][nt][0], c[mt][nt][1]);
            *(float2*)&C[(size_t)(row + 8) * 1024 + col] =
                make_float2(c[mt][nt][2], c[mt][nt][3]);
        }
    }
}

// ---------------------------------------------------------------------------
// Per-head LayerNorm over last dim S=64, in-place. One warp per (b,t,h) vector.
// ---------------------------------------------------------------------------
__global__ __launch_bounds__(256) void ln_heads(float* __restrict__ buf,
                                                const float* __restrict__ w,
                                                const float* __restrict__ b)
{
    int gw = (blockIdx.x * blockDim.x + threadIdx.x) >> 5;
    int lane = threadIdx.x & 31;
    if (gw >= BT * H) return;

    float* v = buf + (size_t)gw * S;
    float2 x = *(float2*)&v[lane * 2];

    float sum = x.x + x.y;
#pragma unroll
    for (int o = 16; o > 0; o >>= 1) sum += __shfl_xor_sync(0xffffffffu, sum, o);
    float mu = sum * (1.0f / 64.0f);

    float dx = x.x - mu, dy = x.y - mu;
    float vs = dx * dx + dy * dy;
#pragma unroll
    for (int o = 16; o > 0; o >>= 1) vs += __shfl_xor_sync(0xffffffffu, vs, o);
    float rs = rsqrtf(vs * (1.0f / 64.0f) + 1e-5f);

    float2 o2;
    o2.x = dx * rs * w[lane * 2]     + b[lane * 2];
    o2.y = dy * rs * w[lane * 2 + 1] + b[lane * 2 + 1];
    *(float2*)&v[lane * 2] = o2;
}

// ---------------------------------------------------------------------------
// Causal flash attention, fp32 (unchanged from R4 — passing).
// ---------------------------------------------------------------------------
#define LDA 68
__global__ __launch_bounds__(256) void attn(const float* __restrict__ Q,
                                            const float* __restrict__ K,
                                            const float* __restrict__ V,
                                            float* __restrict__ O)
{
    extern __shared__ float sm[];
    float* Qs = sm;                 // [64][LDA]
    float* Ks = sm + 64 * LDA;      // [64][LDA], reused as Ps after scores
    float* Vs = sm + 2 * 64 * LDA;  // [64][LDA]

    const int qt = gridDim.x - 1 - blockIdx.x;   // big tiles launch first
    const int bh = blockIdx.y;
    const int b  = bh >> 4, h = bh & 15;
    const int tid = threadIdx.x;
    const int tg = tid >> 4;
    const int tx = tid & 15;
    const int rq = tg * 4;
    const int ck = tx * 4;

    const size_t qbase = ((size_t)b * T + (size_t)qt * 64) * E + h * S;

    for (int idx = tid; idx < 64 * 16; idx += 256) {
        int r = idx >> 4, c4 = idx & 15;
        *(float4*)&Qs[r * LDA + c4 * 4] =
            *(const float4*)&Q[qbase + (size_t)r * E + c4 * 4];
    }

    float m[4], l[4], acc[4][4];
#pragma unroll
    for (int i = 0; i < 4; i++) {
        m[i] = -1e30f; l[i] = 0.f;
#pragma unroll
        for (int j = 0; j < 4; j++) acc[i][j] = 0.f;
    }

    for (int kt = 0; kt <= qt; kt++) {
        const size_t kbase = ((size_t)b * T + (size_t)kt * 64) * E + h * S;
        __syncthreads();
        for (int idx = tid; idx < 64 * 16; idx += 256) {
            int r = idx >> 4, c4 = idx & 15;
            *(float4*)&Ks[r * LDA + c4 * 4] =
                *(const float4*)&K[kbase + (size_t)r * E + c4 * 4];
            *(float4*)&Vs[r * LDA + c4 * 4] =
                *(const float4*)&V[kbase + (size_t)r * E + c4 * 4];
        }
        __syncthreads();

        float s[4][4];
#pragma unroll
        for (int i = 0; i < 4; i++)
#pragma unroll
            for (int j = 0; j < 4; j++) s[i][j] = 0.f;

#pragma unroll 4
        for (int k4 = 0; k4 < 64; k4 += 4) {
            float qv[4][4], kv[4][4];
#pragma unroll
            for (int i = 0; i < 4; i++)
                *(float4*)qv[i] = *(const float4*)&Qs[(rq + i) * LDA + k4];
#pragma unroll
            for (int j = 0; j < 4; j++)
                *(float4*)kv[j] = *(const float4*)&Ks[(tx + 16 * j) * LDA + k4];
#pragma unroll
            for (int i = 0; i < 4; i++)
#pragma unroll
                for (int j = 0; j < 4; j++)
#pragma unroll
                    for (int kk = 0; kk < 4; kk++)
                        s[i][j] += qv[i][kk] * kv[j][kk];
        }

        const bool diag = (kt == qt);
#pragma unroll
        for (int i = 0; i < 4; i++) {
#pragma unroll
            for (int j = 0; j < 4; j++) {
                float sv = s[i][j] * 0.125f;
                if (diag && (tx + 16 * j > rq + i)) sv = -1e30f;
                s[i][j] = sv;
            }
            float rmax = fmaxf(fmaxf(s[i][0], s[i][1]), fmaxf(s[i][2], s[i][3]));
#pragma unroll
            for (int o = 8; o > 0; o >>= 1)
                rmax = fmaxf(rmax, __shfl_xor_sync(0xffffffffu, rmax, o));
            float mnew = fmaxf(m[i], rmax);
            float rsum = 0.f;
#pragma unroll
            for (int j = 0; j < 4; j++) {
                s[i][j] = __expf(s[i][j] - mnew);
                rsum += s[i][j];
            }
#pragma unroll
            for (int o = 8; o > 0; o >>= 1)
                rsum += __shfl_xor_sync(0xffffffffu, rsum, o);
            float alpha = __expf(m[i] - mnew);
            m[i] = mnew;
            l[i] = l[i] * alpha + rsum;
#pragma unroll
            for (int j = 0; j < 4; j++) acc[i][j] *= alpha;
        }

        __syncthreads();
#pragma unroll
        for (int i = 0; i < 4; i++)
#pragma unroll
            for (int j = 0; j < 4; j++)
                Ks[(rq + i) * LDA + tx + 16 * j] = s[i][j];
        __syncthreads();

#pragma unroll 4
        for (int c = 0; c < 64; c += 4) {
            float vv[4][4];
#pragma unroll
            for (int cc = 0; cc < 4; cc++)
                *(float4*)vv[cc] = *(const float4*)&Vs[(c + cc) * LDA + ck];
#pragma unroll
            for (int i = 0; i < 4; i++) {
                float pr[4];
                *(float4*)pr = *(const float4*)&Ks[(rq + i) * LDA + c];
#pragma unroll
                for (int cc = 0; cc < 4; cc++)
#pragma unroll
                    for (int j = 0; j < 4; j++)
                        acc[i][j] += pr[cc] * vv[cc][j];
            }
        }
    }

#pragma unroll
    for (int i = 0; i < 4; i++) {
        float inv = 1.0f / l[i];
        float4 v = make_float4(acc[i][0] * inv, acc[i][1] * inv,
                               acc[i][2] * inv, acc[i][3] * inv);
        *(float4*)&O[qbase + (size_t)(rq + i) * E + ck] = v;
    }
}

// ---------------------------------------------------------------------------
extern "C" void kernel_launch(void* const* d_in, const int* in_sizes, int n_in,
                              void* d_out, int out_size)
{
    const float* x    = (const float*)d_in[0];
    const float* Wk   = (const float*)d_in[1];
    const float* Wq   = (const float*)d_in[2];
    const float* Wv   = (const float*)d_in[3];
    const float* Wu   = (const float*)d_in[4];
    const float* klnw = (const float*)d_in[5];
    const float* klnb = (const float*)d_in[6];
    const float* qlnw = (const float*)d_in[7];
    const float* qlnb = (const float*)d_in[8];
    float* out = (float*)d_out;

    float *gq, *gk, *gv, *go;
    cudaGetSymbolAddress((void**)&gq, g_Q);
    cudaGetSymbolAddress((void**)&gk, g_K);
    cudaGetSymbolAddress((void**)&gv, g_V);
    cudaGetSymbolAddress((void**)&go, g_O);

    const int attn_smem = 3 * 64 * LDA * (int)sizeof(float);  // 52224 B
    cudaFuncSetAttribute(attn, cudaFuncAttributeMaxDynamicSharedMemorySize, attn_smem);

    dim3 gemm_grid(8, 32);   // N/128, M/128
    gemm_tf32<<<gemm_grid, 256>>>(x, Wq, gq);
    gemm_tf32<<<gemm_grid, 256>>>(x, Wk, gk);
    gemm_tf32<<<gemm_grid, 256>>>(x, Wv, gv);

    ln_heads<<<8192, 256>>>(gq, qlnw, qlnb);
    ln_heads<<<8192, 256>>>(gk, klnw, klnb);

    attn<<<dim3(32, 32), 256, attn_smem>>>(gq, gk, gv, go);

    gemm_tf32<<<gemm_grid, 256>>>(go, Wu, out);
}

// round 8
// speedup vs baseline: 2.7228x; 1.6623x over previous
#include <cuda_runtime.h>
#include <math.h>

#define BT 4096   // b*t
#define T  2048
#define E  1024
#define H  16
#define S  64

// Scratch (allocation-free rule: device globals)
__device__ float g_Q[BT * E];
__device__ float g_K[BT * E];
__device__ float g_V[BT * E];
__device__ float g_O[BT * E];

// ---------------------------------------------------------------------------
// tf32 helpers
// ---------------------------------------------------------------------------
__device__ __forceinline__ unsigned f2tf(float f) {
    unsigned u;
    asm("cvt.rna.tf32.f32 %0, %1;" : "=r"(u) : "f"(f));
    return u;
}
__device__ __forceinline__ unsigned smem_u32(const void* p) {
    return (unsigned)__cvta_generic_to_shared(p);
}
__device__ __forceinline__ void ldsm_x4(unsigned& r0, unsigned& r1,
                                        unsigned& r2, unsigned& r3, unsigned a) {
    asm volatile("ldmatrix.sync.aligned.m8n8.x4.shared.b16 {%0,%1,%2,%3}, [%4];"
                 : "=r"(r0), "=r"(r1), "=r"(r2), "=r"(r3) : "r"(a));
}
__device__ __forceinline__ void ldsm_x2(unsigned& r0, unsigned& r1, unsigned a) {
    asm volatile("ldmatrix.sync.aligned.m8n8.x2.shared.b16 {%0,%1}, [%2];"
                 : "=r"(r0), "=r"(r1) : "r"(a));
}
__device__ __forceinline__ void mma_tf32(float* c, const unsigned* a, const unsigned* b) {
    asm volatile("mma.sync.aligned.m16n8k8.row.col.f32.tf32.tf32.f32 "
                 "{%0,%1,%2,%3}, {%4,%5,%6,%7}, {%8,%9}, {%0,%1,%2,%3};"
                 : "+f"(c[0]), "+f"(c[1]), "+f"(c[2]), "+f"(c[3])
                 : "r"(a[0]), "r"(a[1]), "r"(a[2]), "r"(a[3]),
                   "r"(b[0]), "r"(b[1]));
}

// ---------------------------------------------------------------------------
// GEMM (tf32 tensor cores): C[M,N] = A[M,K] * B[N,K]^T,  K=N=1024. (unchanged)
// ---------------------------------------------------------------------------
#define LDSW 20
__global__ __launch_bounds__(256) void gemm_tf32(const float* __restrict__ A,
                                                 const float* __restrict__ B,
                                                 float* __restrict__ C)
{
    __shared__ __align__(16) unsigned As[128 * LDSW];
    __shared__ __align__(16) unsigned Bs[128 * LDSW];

    const int tid  = threadIdx.x;
    const int lane = tid & 31;
    const int warp = tid >> 5;
    const int wm = (warp & 1) * 64;
    const int wn = (warp >> 1) * 32;
    const int bm = blockIdx.y * 128;
    const int bn = blockIdx.x * 128;

    const int r  = tid >> 2;
    const int c4 = tid & 3;

    float c[4][4][4];
#pragma unroll
    for (int mt = 0; mt < 4; mt++)
#pragma unroll
        for (int nt = 0; nt < 4; nt++)
#pragma unroll
            for (int i = 0; i < 4; i++) c[mt][nt][i] = 0.f;

    const float* Ap0 = A + (size_t)(bm + r) * 1024 + c4 * 4;
    const float* Ap1 = A + (size_t)(bm + r + 64) * 1024 + c4 * 4;
    const float* Bp0 = B + (size_t)(bn + r) * 1024 + c4 * 4;
    const float* Bp1 = B + (size_t)(bn + r + 64) * 1024 + c4 * 4;

    const unsigned a_base = smem_u32(As) + (unsigned)((wm + (lane & 15)) * LDSW * 4
                                                      + ((lane >> 4) & 1) * 16);
    const unsigned b_base = smem_u32(Bs) + (unsigned)((wn + (lane & 7)) * LDSW * 4
                                                      + ((lane >> 3) & 1) * 16);

    float4 pa0 = *(const float4*)Ap0;
    float4 pa1 = *(const float4*)Ap1;
    float4 pb0 = *(const float4*)Bp0;
    float4 pb1 = *(const float4*)Bp1;

    for (int k0 = 0; k0 < 1024; k0 += 16) {
        {
            uint4 u;
            u.x = f2tf(pa0.x); u.y = f2tf(pa0.y); u.z = f2tf(pa0.z); u.w = f2tf(pa0.w);
            *(uint4*)&As[r * LDSW + c4 * 4] = u;
            u.x = f2tf(pa1.x); u.y = f2tf(pa1.y); u.z = f2tf(pa1.z); u.w = f2tf(pa1.w);
            *(uint4*)&As[(r + 64) * LDSW + c4 * 4] = u;
            u.x = f2tf(pb0.x); u.y = f2tf(pb0.y); u.z = f2tf(pb0.z); u.w = f2tf(pb0.w);
            *(uint4*)&Bs[r * LDSW + c4 * 4] = u;
            u.x = f2tf(pb1.x); u.y = f2tf(pb1.y); u.z = f2tf(pb1.z); u.w = f2tf(pb1.w);
            *(uint4*)&Bs[(r + 64) * LDSW + c4 * 4] = u;
        }
        __syncthreads();

        if (k0 + 16 < 1024) {
            pa0 = *(const float4*)(Ap0 + k0 + 16);
            pa1 = *(const float4*)(Ap1 + k0 + 16);
            pb0 = *(const float4*)(Bp0 + k0 + 16);
            pb1 = *(const float4*)(Bp1 + k0 + 16);
        }

#pragma unroll
        for (int ks = 0; ks < 2; ks++) {
            unsigned af[4][4], bf[4][2];
#pragma unroll
            for (int mt = 0; mt < 4; mt++)
                ldsm_x4(af[mt][0], af[mt][1], af[mt][2], af[mt][3],
                        a_base + (unsigned)(mt * 16 * LDSW * 4 + ks * 32));
#pragma unroll
            for (int nt = 0; nt < 4; nt++)
                ldsm_x2(bf[nt][0], bf[nt][1],
                        b_base + (unsigned)(nt * 8 * LDSW * 4 + ks * 32));
#pragma unroll
            for (int mt = 0; mt < 4; mt++)
#pragma unroll
                for (int nt = 0; nt < 4; nt++)
                    mma_tf32(c[mt][nt], af[mt], bf[nt]);
        }
        __syncthreads();
    }

#pragma unroll
    for (int mt = 0; mt < 4; mt++) {
#pragma unroll
        for (int nt = 0; nt < 4; nt++) {
            int row = bm + wm + mt * 16 + (lane >> 2);
            int col = bn + wn + nt * 8 + (lane & 3) * 2;
            *(float2*)&C[(size_t)row * 1024 + col] =
                make_float2(c[mt][nt][0], c[mt][nt][1]);
            *(float2*)&C[(size_t)(row + 8) * 1024 + col] =
                make_float2(c[mt][nt][2], c[mt][nt][3]);
        }
    }
}

// ---------------------------------------------------------------------------
// Per-head LayerNorm over last dim S=64, in-place. (unchanged)
// ---------------------------------------------------------------------------
__global__ __launch_bounds__(256) void ln_heads(float* __restrict__ buf,
                                                const float* __restrict__ w,
                                                const float* __restrict__ b)
{
    int gw = (blockIdx.x * blockDim.x + threadIdx.x) >> 5;
    int lane = threadIdx.x & 31;
    if (gw >= BT * H) return;

    float* v = buf + (size_t)gw * S;
    float2 x = *(float2*)&v[lane * 2];

    float sum = x.x + x.y;
#pragma unroll
    for (int o = 16; o > 0; o >>= 1) sum += __shfl_xor_sync(0xffffffffu, sum, o);
    float mu = sum * (1.0f / 64.0f);

    float dx = x.x - mu, dy = x.y - mu;
    float vs = dx * dx + dy * dy;
#pragma unroll
    for (int o = 16; o > 0; o >>= 1) vs += __shfl_xor_sync(0xffffffffu, vs, o);
    float rs = rsqrtf(vs * (1.0f / 64.0f) + 1e-5f);

    float2 o2;
    o2.x = dx * rs * w[lane * 2]     + b[lane * 2];
    o2.y = dy * rs * w[lane * 2 + 1] + b[lane * 2 + 1];
    *(float2*)&v[lane * 2] = o2;
}

// ---------------------------------------------------------------------------
// Causal flash attention on tf32 tensor cores.
// Block = 128 threads (4 warps), 64-query tile per block, 64-key tiles.
// Warp w owns query rows [16w, 16w+16). Q fragments register-resident;
// Q smem buffer aliased as P buffer (per-warp private rows).
// Ks/Qs pad 68 (ldmatrix conflict-free); Vs pad 72 (LDS.32 B-frags conflict-free).
// ---------------------------------------------------------------------------
#define LDK 68
#define LDV 72
__global__ __launch_bounds__(128) void attn(const float* __restrict__ Q,
                                            const float* __restrict__ K,
                                            const float* __restrict__ V,
                                            float* __restrict__ O)
{
    extern __shared__ unsigned smx[];
    unsigned* Qs = smx;                  // [64][LDK] tf32; becomes Ps after Qf load
    unsigned* Ks = smx + 64 * LDK;       // [64][LDK] tf32
    unsigned* Vs = smx + 2 * 64 * LDK;   // [64][LDV] tf32

    const int qt = gridDim.x - 1 - blockIdx.x;   // big tiles first
    const int bh = blockIdx.y;
    const int b  = bh >> 4, h = bh & 15;
    const int tid  = threadIdx.x;
    const int lane = tid & 31;
    const int w    = tid >> 5;           // warp 0..3 -> q rows 16w..16w+15

    const size_t qbase = ((size_t)b * T + (size_t)qt * 64) * E + h * S;

    // ---- stage Q tile (tf32) ----
    for (int idx = tid; idx < 64 * 16; idx += 128) {
        int r = idx >> 4, c4 = idx & 15;
        float4 v = *(const float4*)&Q[qbase + (size_t)r * E + c4 * 4];
        uint4 u;
        u.x = f2tf(v.x); u.y = f2tf(v.y); u.z = f2tf(v.z); u.w = f2tf(v.w);
        *(uint4*)&Qs[r * LDK + c4 * 4] = u;
    }
    __syncthreads();

    // ---- load Q fragments (resident for whole block) ----
    const unsigned a_base = smem_u32(Qs) +
        (unsigned)((16 * w + (lane & 15)) * LDK * 4 + ((lane >> 4) & 1) * 16);
    unsigned Qf[8][4];
#pragma unroll
    for (int ks = 0; ks < 8; ks++)
        ldsm_x4(Qf[ks][0], Qf[ks][1], Qf[ks][2], Qf[ks][3],
                a_base + (unsigned)(ks * 32));

    // B-frag base for K (pairs of n-tiles per ldsm_x4)
    const unsigned kb_base = smem_u32(Ks) +
        (unsigned)((((lane >> 4) * 8) + (lane & 7)) * LDK * 4 + ((lane >> 3) & 1) * 16);
    // V B-frag pointer: b0 = V[key = 8ks + (lane&3)][dim = 8nt + (lane>>2)]
    const unsigned* Vp = Vs + (lane & 3) * LDV + (lane >> 2);

    float o[8][4];
    float m[2], l[2];
#pragma unroll
    for (int nt = 0; nt < 8; nt++)
#pragma unroll
        for (int i = 0; i < 4; i++) o[nt][i] = 0.f;
    m[0] = m[1] = -1e30f;
    l[0] = l[1] = 0.f;

    const int row0 = (lane >> 2);        // thread's row (tile-local = 16w + row0 [+8])
    const int colb = 2 * (lane & 3);     // thread's col base within n-tile

    for (int kt = 0; kt <= qt; kt++) {
        const size_t kbase = ((size_t)b * T + (size_t)kt * 64) * E + h * S;
        __syncthreads();   // prior iteration done reading Ks/Vs
        for (int idx = tid; idx < 64 * 16; idx += 128) {
            int r = idx >> 4, c4 = idx & 15;
            float4 kv = *(const float4*)&K[kbase + (size_t)r * E + c4 * 4];
            float4 vv = *(const float4*)&V[kbase + (size_t)r * E + c4 * 4];
            uint4 u;
            u.x = f2tf(kv.x); u.y = f2tf(kv.y); u.z = f2tf(kv.z); u.w = f2tf(kv.w);
            *(uint4*)&Ks[r * LDK + c4 * 4] = u;
            u.x = f2tf(vv.x); u.y = f2tf(vv.y); u.z = f2tf(vv.z); u.w = f2tf(vv.w);
            *(uint4*)&Vs[r * LDV + c4 * 4] = u;
        }
        __syncthreads();

        // ---- S = Q K^T  (warp: 16 rows x 64 keys) ----
        float s[8][4];
#pragma unroll
        for (int nt = 0; nt < 8; nt++)
#pragma unroll
            for (int i = 0; i < 4; i++) s[nt][i] = 0.f;

#pragma unroll
        for (int ks = 0; ks < 8; ks++) {
            unsigned bf[8][2];
#pragma unroll
            for (int p = 0; p < 4; p++)
                ldsm_x4(bf[2 * p][0], bf[2 * p][1], bf[2 * p + 1][0], bf[2 * p + 1][1],
                        kb_base + (unsigned)(p * 16 * LDK * 4 + ks * 32));
#pragma unroll
            for (int nt = 0; nt < 8; nt++)
                mma_tf32(s[nt], Qf[ks], bf[nt]);
        }

        // ---- online softmax on fragments ----
        const bool diag = (kt == qt);
#pragma unroll
        for (int hh = 0; hh < 2; hh++) {
            const int rloc = 16 * w + row0 + 8 * hh;   // tile-local query row
            float rmax = -1e30f;
#pragma unroll
            for (int nt = 0; nt < 8; nt++) {
#pragma unroll
                for (int e = 0; e < 2; e++) {
                    float sv = s[nt][2 * hh + e] * 0.125f;
                    if (diag && (8 * nt + colb + e > rloc)) sv = -1e30f;
                    s[nt][2 * hh + e] = sv;
                    rmax = fmaxf(rmax, sv);
                }
            }
            rmax = fmaxf(rmax, __shfl_xor_sync(0xffffffffu, rmax, 1));
            rmax = fmaxf(rmax, __shfl_xor_sync(0xffffffffu, rmax, 2));
            float mnew = fmaxf(m[hh], rmax);
            float alpha = __expf(m[hh] - mnew);
            m[hh] = mnew;
            float rsum = 0.f;
#pragma unroll
            for (int nt = 0; nt < 8; nt++) {
#pragma unroll
                for (int e = 0; e < 2; e++) {
                    float p = __expf(s[nt][2 * hh + e] - mnew);
                    s[nt][2 * hh + e] = p;
                    rsum += p;
                }
            }
            rsum += __shfl_xor_sync(0xffffffffu, rsum, 1);
            rsum += __shfl_xor_sync(0xffffffffu, rsum, 2);
            l[hh] = l[hh] * alpha + rsum;
#pragma unroll
            for (int nt = 0; nt < 8; nt++) {
                o[nt][2 * hh]     *= alpha;
                o[nt][2 * hh + 1] *= alpha;
            }
        }

        // ---- store P (tf32) into aliased Qs buffer; per-warp-private rows ----
        __syncwarp();
#pragma unroll
        for (int nt = 0; nt < 8; nt++) {
            unsigned* p0 = &Qs[(16 * w + row0) * LDK + 8 * nt + colb];
            unsigned* p1 = &Qs[(16 * w + row0 + 8) * LDK + 8 * nt + colb];
            *(uint2*)p0 = make_uint2(f2tf(s[nt][0]), f2tf(s[nt][1]));
            *(uint2*)p1 = make_uint2(f2tf(s[nt][2]), f2tf(s[nt][3]));
        }
        __syncwarp();

        // ---- O += P V ----
#pragma unroll
        for (int ks = 0; ks < 8; ks++) {
            unsigned pa[4];
            ldsm_x4(pa[0], pa[1], pa[2], pa[3], a_base + (unsigned)(ks * 32));
            const unsigned* vrow = Vp + ks * 8 * LDV;
#pragma unroll
            for (int nt = 0; nt < 8; nt++) {
                unsigned bv[2];
                bv[0] = vrow[nt * 8];
                bv[1] = vrow[nt * 8 + 4 * LDV];
                mma_tf32(o[nt], pa, bv);
            }
        }
    }

    // ---- epilogue ----
    const float inv0 = 1.0f / l[0];
    const float inv1 = 1.0f / l[1];
    const size_t r0g = qbase + (size_t)(16 * w + row0) * E;
    const size_t r1g = qbase + (size_t)(16 * w + row0 + 8) * E;
#pragma unroll
    for (int nt = 0; nt < 8; nt++) {
        int col = 8 * nt + colb;
        *(float2*)&O[r0g + col] = make_float2(o[nt][0] * inv0, o[nt][1] * inv0);
        *(float2*)&O[r1g + col] = make_float2(o[nt][2] * inv1, o[nt][3] * inv1);
    }
}

// ---------------------------------------------------------------------------
extern "C" void kernel_launch(void* const* d_in, const int* in_sizes, int n_in,
                              void* d_out, int out_size)
{
    const float* x    = (const float*)d_in[0];
    const float* Wk   = (const float*)d_in[1];
    const float* Wq   = (const float*)d_in[2];
    const float* Wv   = (const float*)d_in[3];
    const float* Wu   = (const float*)d_in[4];
    const float* klnw = (const float*)d_in[5];
    const float* klnb = (const float*)d_in[6];
    const float* qlnw = (const float*)d_in[7];
    const float* qlnb = (const float*)d_in[8];
    float* out = (float*)d_out;

    float *gq, *gk, *gv, *go;
    cudaGetSymbolAddress((void**)&gq, g_Q);
    cudaGetSymbolAddress((void**)&gk, g_K);
    cudaGetSymbolAddress((void**)&gv, g_V);
    cudaGetSymbolAddress((void**)&go, g_O);

    const int attn_smem = (2 * 64 * LDK + 64 * LDV) * (int)sizeof(unsigned); // 53248
    cudaFuncSetAttribute(attn, cudaFuncAttributeMaxDynamicSharedMemorySize, attn_smem);

    dim3 gemm_grid(8, 32);   // N/128, M/128
    gemm_tf32<<<gemm_grid, 256>>>(x, Wq, gq);
    gemm_tf32<<<gemm_grid, 256>>>(x, Wk, gk);
    gemm_tf32<<<gemm_grid, 256>>>(x, Wv, gv);

    ln_heads<<<8192, 256>>>(gq, qlnw, qlnb);
    ln_heads<<<8192, 256>>>(gk, klnw, klnb);

    attn<<<dim3(32, 32), 128, attn_smem>>>(gq, gk, gv, go);

    gemm_tf32<<<gemm_grid, 256>>>(go, Wu, out);
}

// round 11
// speedup vs baseline: 3.0042x; 1.1034x over previous
#include <cuda_runtime.h>
#include <math.h>
#include <stdint.h>

#define BT 4096   // b*t
#define T  2048
#define E  1024
#define H  16
#define S  64

// Scratch (allocation-free rule: device globals)
__device__ float g_Q[BT * E];
__device__ float g_K[BT * E];
__device__ float g_V[BT * E];
__device__ float g_O[BT * E];
__device__ float g_X[BT * E];    // tf32-rounded x
__device__ float g_Wq[E * E];    // tf32-rounded weights
__device__ float g_Wk[E * E];
__device__ float g_Wv[E * E];
__device__ float g_Wu[E * E];

// ---------------------------------------------------------------------------
// helpers
// ---------------------------------------------------------------------------
__device__ __forceinline__ unsigned f2tf(float f) {
    unsigned u;
    asm("cvt.rna.tf32.f32 %0, %1;" : "=r"(u) : "f"(f));
    return u;
}
__device__ __forceinline__ unsigned smem_u32(const void* p) {
    return (unsigned)__cvta_generic_to_shared(p);
}
__device__ __forceinline__ void ldsm_x4(unsigned& r0, unsigned& r1,
                                        unsigned& r2, unsigned& r3, unsigned a) {
    asm volatile("ldmatrix.sync.aligned.m8n8.x4.shared.b16 {%0,%1,%2,%3}, [%4];"
                 : "=r"(r0), "=r"(r1), "=r"(r2), "=r"(r3) : "r"(a));
}
__device__ __forceinline__ void ldsm_x2(unsigned& r0, unsigned& r1, unsigned a) {
    asm volatile("ldmatrix.sync.aligned.m8n8.x2.shared.b16 {%0,%1}, [%2];"
                 : "=r"(r0), "=r"(r1) : "r"(a));
}
__device__ __forceinline__ void mma_tf32(float* c, const unsigned* a, const unsigned* b) {
    asm volatile("mma.sync.aligned.m16n8k8.row.col.f32.tf32.tf32.f32 "
                 "{%0,%1,%2,%3}, {%4,%5,%6,%7}, {%8,%9}, {%0,%1,%2,%3};"
                 : "+f"(c[0]), "+f"(c[1]), "+f"(c[2]), "+f"(c[3])
                 : "r"(a[0]), "r"(a[1]), "r"(a[2]), "r"(a[3]),
                   "r"(b[0]), "r"(b[1]));
}
#define CP_ASYNC16(dst, src) \
    asm volatile("cp.async.cg.shared.global [%0], [%1], 16;" :: "r"(dst), "l"(src))
#define CP_COMMIT() asm volatile("cp.async.commit_group;")
#define CP_WAIT(n)  asm volatile("cp.async.wait_group %0;" :: "n"(n))

// ---------------------------------------------------------------------------
// Pre-round fp32 -> tf32-valued fp32 (elementwise, float4)
// ---------------------------------------------------------------------------
__global__ __launch_bounds__(256) void round_tf32(const float* __restrict__ src,
                                                  float* __restrict__ dst, int n4)
{
    int i = blockIdx.x * blockDim.x + threadIdx.x;
    if (i >= n4) return;
    float4 v = ((const float4*)src)[i];
    float4 o;
    o.x = __uint_as_float(f2tf(v.x));
    o.y = __uint_as_float(f2tf(v.y));
    o.z = __uint_as_float(f2tf(v.z));
    o.w = __uint_as_float(f2tf(v.w));
    ((float4*)dst)[i] = o;
}

// ---------------------------------------------------------------------------
// GEMM (mma.sync tf32 + 3-stage cp.async): C[M,N] = A[M,K]*B[N,K]^T, K=N=1024.
// Inputs must already be tf32-valued. Block 128x128, BK=16, 256 threads,
// 8 warps (2x4), warp tile 64x32. Smem layout identical to R8 (LDSW=20 pad).
// ---------------------------------------------------------------------------
#define LDSW 20
#define STG_W (128 * LDSW)                 // words per tile per stage
#define NSTG 3
#define NK 64                              // 1024 / 16

__global__ __launch_bounds__(256) void gemm_tf32(const float* __restrict__ A,
                                                 const float* __restrict__ B,
                                                 float* __restrict__ C)
{
    extern __shared__ __align__(16) unsigned smg[];
    unsigned* As = smg;                    // [NSTG][STG_W]
    unsigned* Bs = smg + NSTG * STG_W;     // [NSTG][STG_W]

    const int tid  = threadIdx.x;
    const int lane = tid & 31;
    const int warp = tid >> 5;
    const int wm = (warp & 1) * 64;
    const int wn = (warp >> 1) * 32;
    const int bm = blockIdx.y * 128;
    const int bn = blockIdx.x * 128;

    float c[4][4][4];
#pragma unroll
    for (int mt = 0; mt < 4; mt++)
#pragma unroll
        for (int nt = 0; nt < 4; nt++)
#pragma unroll
            for (int i = 0; i < 4; i++) c[mt][nt][i] = 0.f;

    // copy assignment: thread handles A chunks {tid, tid+256}, B likewise.
    const int r0 = tid >> 2, c40 = tid & 3;          // chunk 0: row r0
    const unsigned adst0 = smem_u32(As) + (unsigned)(r0 * LDSW + c40 * 4) * 4;
    const unsigned adst1 = adst0 + (unsigned)(64 * LDSW * 4);
    const unsigned bdst0 = smem_u32(Bs) + (unsigned)(r0 * LDSW + c40 * 4) * 4;
    const unsigned bdst1 = bdst0 + (unsigned)(64 * LDSW * 4);
    const float* asrc0 = A + (size_t)(bm + r0) * 1024 + c40 * 4;
    const float* asrc1 = asrc0 + (size_t)64 * 1024;
    const float* bsrc0 = B + (size_t)(bn + r0) * 1024 + c40 * 4;
    const float* bsrc1 = bsrc0 + (size_t)64 * 1024;

    auto issue = [&](int cs) {
        const unsigned so = (unsigned)((cs % NSTG) * STG_W * 4);  // bytes
        const int ko = cs * 16;
        CP_ASYNC16(adst0 + so, asrc0 + ko);
        CP_ASYNC16(adst1 + so, asrc1 + ko);
        CP_ASYNC16(bdst0 + so, bsrc0 + ko);
        CP_ASYNC16(bdst1 + so, bsrc1 + ko);
        CP_COMMIT();
    };

    issue(0);
    issue(1);

    const unsigned a_base0 = smem_u32(As) + (unsigned)((wm + (lane & 15)) * LDSW * 4
                                                       + ((lane >> 4) & 1) * 16);
    const unsigned b_base0 = smem_u32(Bs) + (unsigned)((wn + (lane & 7)) * LDSW * 4
                                                       + ((lane >> 3) & 1) * 16);

    for (int i = 0; i < NK; i++) {
        if (i == NK - 1) { CP_WAIT(0); } else { CP_WAIT(1); }
        __syncthreads();
        if (i + 2 < NK) issue(i + 2);

        const unsigned so = (unsigned)((i % NSTG) * STG_W * 4);
        const unsigned a_base = a_base0 + so;
        const unsigned b_base = b_base0 + so;
#pragma unroll
        for (int ks = 0; ks < 2; ks++) {
            unsigned af[4][4], bf[4][2];
#pragma unroll
            for (int mt = 0; mt < 4; mt++)
                ldsm_x4(af[mt][0], af[mt][1], af[mt][2], af[mt][3],
                        a_base + (unsigned)(mt * 16 * LDSW * 4 + ks * 32));
#pragma unroll
            for (int nt = 0; nt < 4; nt++)
                ldsm_x2(bf[nt][0], bf[nt][1],
                        b_base + (unsigned)(nt * 8 * LDSW * 4 + ks * 32));
#pragma unroll
            for (int mt = 0; mt < 4; mt++)
#pragma unroll
                for (int nt = 0; nt < 4; nt++)
                    mma_tf32(c[mt][nt], af[mt], bf[nt]);
        }
    }

#pragma unroll
    for (int mt = 0; mt < 4; mt++) {
#pragma unroll
        for (int nt = 0; nt < 4; nt++) {
            int row = bm + wm + mt * 16 + (lane >> 2);
            int col = bn + wn + nt * 8 + (lane & 3) * 2;
            *(float2*)&C[(size_t)row * 1024 + col] =
                make_float2(c[mt][nt][0], c[mt][nt][1]);
            *(float2*)&C[(size_t)(row + 8) * 1024 + col] =
                make_float2(c[mt][nt][2], c[mt][nt][3]);
        }
    }
}

// ---------------------------------------------------------------------------
// Per-head LayerNorm over last dim S=64, in-place. (unchanged)
// ---------------------------------------------------------------------------
__global__ __launch_bounds__(256) void ln_heads(float* __restrict__ buf,
                                                const float* __restrict__ w,
                                                const float* __restrict__ b)
{
    int gw = (blockIdx.x * blockDim.x + threadIdx.x) >> 5;
    int lane = threadIdx.x & 31;
    if (gw >= BT * H) return;

    float* v = buf + (size_t)gw * S;
    float2 x = *(float2*)&v[lane * 2];

    float sum = x.x + x.y;
#pragma unroll
    for (int o = 16; o > 0; o >>= 1) sum += __shfl_xor_sync(0xffffffffu, sum, o);
    float mu = sum * (1.0f / 64.0f);

    float dx = x.x - mu, dy = x.y - mu;
    float vs = dx * dx + dy * dy;
#pragma unroll
    for (int o = 16; o > 0; o >>= 1) vs += __shfl_xor_sync(0xffffffffu, vs, o);
    float rs = rsqrtf(vs * (1.0f / 64.0f) + 1e-5f);

    float2 o2;
    o2.x = dx * rs * w[lane * 2]     + b[lane * 2];
    o2.y = dy * rs * w[lane * 2 + 1] + b[lane * 2 + 1];
    *(float2*)&v[lane * 2] = o2;
}

// ---------------------------------------------------------------------------
// Causal flash attention on tf32 mma.sync (R8-passing; epilogue now stores
// tf32-rounded O so the final GEMM can skip conversion).
// ---------------------------------------------------------------------------
#define LDK 68
#define LDV 72
__global__ __launch_bounds__(128) void attn(const float* __restrict__ Q,
                                            const float* __restrict__ K,
                                            const float* __restrict__ V,
                                            float* __restrict__ O)
{
    extern __shared__ unsigned smx[];
    unsigned* Qs = smx;
    unsigned* Ks = smx + 64 * LDK;
    unsigned* Vs = smx + 2 * 64 * LDK;

    const int qt = gridDim.x - 1 - blockIdx.x;
    const int bh = blockIdx.y;
    const int b  = bh >> 4, h = bh & 15;
    const int tid  = threadIdx.x;
    const int lane = tid & 31;
    const int w    = tid >> 5;

    const size_t qbase = ((size_t)b * T + (size_t)qt * 64) * E + h * S;

    for (int idx = tid; idx < 64 * 16; idx += 128) {
        int r = idx >> 4, c4 = idx & 15;
        float4 v = *(const float4*)&Q[qbase + (size_t)r * E + c4 * 4];
        uint4 u;
        u.x = f2tf(v.x); u.y = f2tf(v.y); u.z = f2tf(v.z); u.w = f2tf(v.w);
        *(uint4*)&Qs[r * LDK + c4 * 4] = u;
    }
    __syncthreads();

    const unsigned a_base = smem_u32(Qs) +
        (unsigned)((16 * w + (lane & 15)) * LDK * 4 + ((lane >> 4) & 1) * 16);
    unsigned Qf[8][4];
#pragma unroll
    for (int ks = 0; ks < 8; ks++)
        ldsm_x4(Qf[ks][0], Qf[ks][1], Qf[ks][2], Qf[ks][3],
                a_base + (unsigned)(ks * 32));

    const unsigned kb_base = smem_u32(Ks) +
        (unsigned)((((lane >> 4) * 8) + (lane & 7)) * LDK * 4 + ((lane >> 3) & 1) * 16);
    const unsigned* Vp = Vs + (lane & 3) * LDV + (lane >> 2);

    float o[8][4];
    float m[2], l[2];
#pragma unroll
    for (int nt = 0; nt < 8; nt++)
#pragma unroll
        for (int i = 0; i < 4; i++) o[nt][i] = 0.f;
    m[0] = m[1] = -1e30f;
    l[0] = l[1] = 0.f;

    const int row0 = (lane >> 2);
    const int colb = 2 * (lane & 3);

    for (int kt = 0; kt <= qt; kt++) {
        const size_t kbase = ((size_t)b * T + (size_t)kt * 64) * E + h * S;
        __syncthreads();
        for (int idx = tid; idx < 64 * 16; idx += 128) {
            int r = idx >> 4, c4 = idx & 15;
            float4 kv = *(const float4*)&K[kbase + (size_t)r * E + c4 * 4];
            float4 vv = *(const float4*)&V[kbase + (size_t)r * E + c4 * 4];
            uint4 u;
            u.x = f2tf(kv.x); u.y = f2tf(kv.y); u.z = f2tf(kv.z); u.w = f2tf(kv.w);
            *(uint4*)&Ks[r * LDK + c4 * 4] = u;
            u.x = f2tf(vv.x); u.y = f2tf(vv.y); u.z = f2tf(vv.z); u.w = f2tf(vv.w);
            *(uint4*)&Vs[r * LDV + c4 * 4] = u;
        }
        __syncthreads();

        float s[8][4];
#pragma unroll
        for (int nt = 0; nt < 8; nt++)
#pragma unroll
            for (int i = 0; i < 4; i++) s[nt][i] = 0.f;

#pragma unroll
        for (int ks = 0; ks < 8; ks++) {
            unsigned bf[8][2];
#pragma unroll
            for (int p = 0; p < 4; p++)
                ldsm_x4(bf[2 * p][0], bf[2 * p][1], bf[2 * p + 1][0], bf[2 * p + 1][1],
                        kb_base + (unsigned)(p * 16 * LDK * 4 + ks * 32));
#pragma unroll
            for (int nt = 0; nt < 8; nt++)
                mma_tf32(s[nt], Qf[ks], bf[nt]);
        }

        const bool diag = (kt == qt);
#pragma unroll
        for (int hh = 0; hh < 2; hh++) {
            const int rloc = 16 * w + row0 + 8 * hh;
            float rmax = -1e30f;
#pragma unroll
            for (int nt = 0; nt < 8; nt++) {
#pragma unroll
                for (int e = 0; e < 2; e++) {
                    float sv = s[nt][2 * hh + e] * 0.125f;
                    if (diag && (8 * nt + colb + e > rloc)) sv = -1e30f;
                    s[nt][2 * hh + e] = sv;
                    rmax = fmaxf(rmax, sv);
                }
            }
            rmax = fmaxf(rmax, __shfl_xor_sync(0xffffffffu, rmax, 1));
            rmax = fmaxf(rmax, __shfl_xor_sync(0xffffffffu, rmax, 2));
            float mnew = fmaxf(m[hh], rmax);
            float alpha = __expf(m[hh] - mnew);
            m[hh] = mnew;
            float rsum = 0.f;
#pragma unroll
            for (int nt = 0; nt < 8; nt++) {
#pragma unroll
                for (int e = 0; e < 2; e++) {
                    float p = __expf(s[nt][2 * hh + e] - mnew);
                    s[nt][2 * hh + e] = p;
                    rsum += p;
                }
            }
            rsum += __shfl_xor_sync(0xffffffffu, rsum, 1);
            rsum += __shfl_xor_sync(0xffffffffu, rsum, 2);
            l[hh] = l[hh] * alpha + rsum;
#pragma unroll
            for (int nt = 0; nt < 8; nt++) {
                o[nt][2 * hh]     *= alpha;
                o[nt][2 * hh + 1] *= alpha;
            }
        }

        __syncwarp();
#pragma unroll
        for (int nt = 0; nt < 8; nt++) {
            unsigned* p0 = &Qs[(16 * w + row0) * LDK + 8 * nt + colb];
            unsigned* p1 = &Qs[(16 * w + row0 + 8) * LDK + 8 * nt + colb];
            *(uint2*)p0 = make_uint2(f2tf(s[nt][0]), f2tf(s[nt][1]));
            *(uint2*)p1 = make_uint2(f2tf(s[nt][2]), f2tf(s[nt][3]));
        }
        __syncwarp();

#pragma unroll
        for (int ks = 0; ks < 8; ks++) {
            unsigned pa[4];
            ldsm_x4(pa[0], pa[1], pa[2], pa[3], a_base + (unsigned)(ks * 32));
            const unsigned* vrow = Vp + ks * 8 * LDV;
#pragma unroll
            for (int nt = 0; nt < 8; nt++) {
                unsigned bv[2];
                bv[0] = vrow[nt * 8];
                bv[1] = vrow[nt * 8 + 4 * LDV];
                mma_tf32(o[nt], pa, bv);
            }
        }
    }

    // epilogue: store tf32-rounded O (final GEMM consumes it directly)
    const float inv0 = 1.0f / l[0];
    const float inv1 = 1.0f / l[1];
    const size_t r0g = qbase + (size_t)(16 * w + row0) * E;
    const size_t r1g = qbase + (size_t)(16 * w + row0 + 8) * E;
#pragma unroll
    for (int nt = 0; nt < 8; nt++) {
        int col = 8 * nt + colb;
        *(float2*)&O[r0g + col] =
            make_float2(__uint_as_float(f2tf(o[nt][0] * inv0)),
                        __uint_as_float(f2tf(o[nt][1] * inv0)));
        *(float2*)&O[r1g + col] =
            make_float2(__uint_as_float(f2tf(o[nt][2] * inv1)),
                        __uint_as_float(f2tf(o[nt][3] * inv1)));
    }
}

// ---------------------------------------------------------------------------
extern "C" void kernel_launch(void* const* d_in, const int* in_sizes, int n_in,
                              void* d_out, int out_size)
{
    const float* x    = (const float*)d_in[0];
    const float* Wk   = (const float*)d_in[1];
    const float* Wq   = (const float*)d_in[2];
    const float* Wv   = (const float*)d_in[3];
    const float* Wu   = (const float*)d_in[4];
    const float* klnw = (const float*)d_in[5];
    const float* klnb = (const float*)d_in[6];
    const float* qlnw = (const float*)d_in[7];
    const float* qlnb = (const float*)d_in[8];
    float* out = (float*)d_out;

    float *gq, *gk, *gv, *go, *gx, *gwq, *gwk, *gwv, *gwu;
    cudaGetSymbolAddress((void**)&gq,  g_Q);
    cudaGetSymbolAddress((void**)&gk,  g_K);
    cudaGetSymbolAddress((void**)&gv,  g_V);
    cudaGetSymbolAddress((void**)&go,  g_O);
    cudaGetSymbolAddress((void**)&gx,  g_X);
    cudaGetSymbolAddress((void**)&gwq, g_Wq);
    cudaGetSymbolAddress((void**)&gwk, g_Wk);
    cudaGetSymbolAddress((void**)&gwv, g_Wv);
    cudaGetSymbolAddress((void**)&gwu, g_Wu);

    const int attn_smem = (2 * 64 * LDK + 64 * LDV) * (int)sizeof(unsigned); // 53248
    const int gemm_smem = 2 * NSTG * STG_W * (int)sizeof(unsigned);          // 61440
    cudaFuncSetAttribute(attn, cudaFuncAttributeMaxDynamicSharedMemorySize, attn_smem);
    cudaFuncSetAttribute(gemm_tf32, cudaFuncAttributeMaxDynamicSharedMemorySize, gemm_smem);

    // pre-round inputs to tf32 values
    round_tf32<<<(BT * E / 4 + 255) / 256, 256>>>(x, gx, BT * E / 4);
    round_tf32<<<(E * E / 4 + 255) / 256, 256>>>(Wq, gwq, E * E / 4);
    round_tf32<<<(E * E / 4 + 255) / 256, 256>>>(Wk, gwk, E * E / 4);
    round_tf32<<<(E * E / 4 + 255) / 256, 256>>>(Wv, gwv, E * E / 4);
    round_tf32<<<(E * E / 4 + 255) / 256, 256>>>(Wu, gwu, E * E / 4);

    dim3 gemm_grid(8, 32);   // N/128, M/128
    gemm_tf32<<<gemm_grid, 256, gemm_smem>>>(gx, gwq, gq);
    gemm_tf32<<<gemm_grid, 256, gemm_smem>>>(gx, gwk, gk);
    gemm_tf32<<<gemm_grid, 256, gemm_smem>>>(gx, gwv, gv);

    ln_heads<<<8192, 256>>>(gq, qlnw, qlnb);
    ln_heads<<<8192, 256>>>(gk, klnw, klnb);

    attn<<<dim3(32, 32), 128, attn_smem>>>(gq, gk, gv, go);

    gemm_tf32<<<gemm_grid, 256, gemm_smem>>>(go, gwu, out);
}

// round 15
// speedup vs baseline: 5.5307x; 1.8410x over previous
#include <cuda_runtime.h>
#include <cuda_fp16.h>
#include <math.h>
#include <stdint.h>

#define BT 4096   // b*t
#define T  2048
#define E  1024
#define H  16
#define S  64

// Scratch (allocation-free rule: device globals), all fp16
__device__ __half g_X16[BT * E];
__device__ __half g_Q16[BT * E];
__device__ __half g_K16[BT * E];
__device__ __half g_V16[BT * E];
__device__ __half g_O16[BT * E];
__device__ __half g_Wq16[E * E];
__device__ __half g_Wk16[E * E];
__device__ __half g_Wv16[E * E];
__device__ __half g_Wu16[E * E];

// ---------------------------------------------------------------------------
// helpers
// ---------------------------------------------------------------------------
__device__ __forceinline__ unsigned smem_u32(const void* p) {
    return (unsigned)__cvta_generic_to_shared(p);
}
__device__ __forceinline__ void ldsm_x4(unsigned& r0, unsigned& r1,
                                        unsigned& r2, unsigned& r3, unsigned a) {
    asm volatile("ldmatrix.sync.aligned.m8n8.x4.shared.b16 {%0,%1,%2,%3}, [%4];"
                 : "=r"(r0), "=r"(r1), "=r"(r2), "=r"(r3) : "r"(a));
}
__device__ __forceinline__ void ldsm_x4t(unsigned& r0, unsigned& r1,
                                         unsigned& r2, unsigned& r3, unsigned a) {
    asm volatile("ldmatrix.sync.aligned.m8n8.x4.trans.shared.b16 {%0,%1,%2,%3}, [%4];"
                 : "=r"(r0), "=r"(r1), "=r"(r2), "=r"(r3) : "r"(a));
}
// fp16 mma: m16n8k16, fp32 accum
__device__ __forceinline__ void mma_f16(float* c, const unsigned* a, const unsigned* b) {
    asm volatile("mma.sync.aligned.m16n8k16.row.col.f32.f16.f16.f32 "
                 "{%0,%1,%2,%3}, {%4,%5,%6,%7}, {%8,%9}, {%0,%1,%2,%3};"
                 : "+f"(c[0]), "+f"(c[1]), "+f"(c[2]), "+f"(c[3])
                 : "r"(a[0]), "r"(a[1]), "r"(a[2]), "r"(a[3]),
                   "r"(b[0]), "r"(b[1]));
}
#define CP_ASYNC16(dst, src) \
    asm volatile("cp.async.cg.shared.global [%0], [%1], 16;" :: "r"(dst), "l"(src))
#define CP_COMMIT() asm volatile("cp.async.commit_group;")
#define CP_WAIT(n)  asm volatile("cp.async.wait_group %0;" :: "n"(n))

// ---------------------------------------------------------------------------
// fp32 -> fp16 conversion, 8 elems/thread
// ---------------------------------------------------------------------------
__global__ __launch_bounds__(256) void cvt_h(const float* __restrict__ src,
                                             __half* __restrict__ dst, int n8)
{
    int i = blockIdx.x * blockDim.x + threadIdx.x;
    if (i >= n8) return;
    float4 a = ((const float4*)src)[2 * i];
    float4 b = ((const float4*)src)[2 * i + 1];
    __half2 h[4];
    h[0] = __floats2half2_rn(a.x, a.y);
    h[1] = __floats2half2_rn(a.z, a.w);
    h[2] = __floats2half2_rn(b.x, b.y);
    h[3] = __floats2half2_rn(b.z, b.w);
    *(uint4*)(dst + (size_t)8 * i) = *(uint4*)h;
}

// ---------------------------------------------------------------------------
// fp16 GEMM: C[M,N] = A[M,K]*B[N,K]^T, K=N=1024. Block 128x128, BK=32 halves,
// 256 threads (8 warps 2x4, warp 64x32), 3-stage cp.async.
// OUTH=1 -> __half C, OUTH=0 -> float C.
// ---------------------------------------------------------------------------
#define LDH 40                      // halves per smem row (80 B)
#define STG_B (128 * 80)            // bytes per tile per stage (10240)
#define NSTG 3
#define NK 32                       // 1024 / 32

template <int OUTH>
__global__ __launch_bounds__(256) void gemm_h(const __half* __restrict__ A,
                                              const __half* __restrict__ B,
                                              void* __restrict__ Cv)
{
    extern __shared__ __align__(16) char smg[];
    const unsigned sA = smem_u32(smg);
    const unsigned sB = sA + NSTG * STG_B;

    const int tid  = threadIdx.x;
    const int lane = tid & 31;
    const int warp = tid >> 5;
    const int wm = (warp & 1) * 64;
    const int wn = (warp >> 1) * 32;
    const int bm = blockIdx.y * 128;
    const int bn = blockIdx.x * 128;

    float c[4][4][4];
#pragma unroll
    for (int mt = 0; mt < 4; mt++)
#pragma unroll
        for (int nt = 0; nt < 4; nt++)
#pragma unroll
            for (int i = 0; i < 4; i++) c[mt][nt][i] = 0.f;

    // copy map: idx in [0,512): r=idx>>2 (row), c=idx&3 (16B chunk = 8 halves)
    const int r0 = tid >> 2, c0 = tid & 3;          // idx = tid
    const int r1 = (tid + 256) >> 2;                // idx = tid+256 (same c)
    const unsigned ad0 = sA + (unsigned)(r0 * 80 + c0 * 16);
    const unsigned ad1 = sA + (unsigned)(r1 * 80 + c0 * 16);
    const unsigned bd0 = sB + (unsigned)(r0 * 80 + c0 * 16);
    const unsigned bd1 = sB + (unsigned)(r1 * 80 + c0 * 16);
    const __half* as0 = A + (size_t)(bm + r0) * 1024 + c0 * 8;
    const __half* as1 = A + (size_t)(bm + r1) * 1024 + c0 * 8;
    const __half* bs0 = B + (size_t)(bn + r0) * 1024 + c0 * 8;
    const __half* bs1 = B + (size_t)(bn + r1) * 1024 + c0 * 8;

    auto issue = [&](int cs) {
        const unsigned so = (unsigned)((cs % NSTG) * STG_B);
        const int ko = cs * 32;
        CP_ASYNC16(ad0 + so, as0 + ko);
        CP_ASYNC16(ad1 + so, as1 + ko);
        CP_ASYNC16(bd0 + so, bs0 + ko);
        CP_ASYNC16(bd1 + so, bs1 + ko);
        CP_COMMIT();
    };

    issue(0);
    issue(1);

    const unsigned a_base0 = sA + (unsigned)((wm + (lane & 15)) * 80
                                             + ((lane >> 4) & 1) * 16);
    const unsigned b_base0 = sB + (unsigned)((wn + (lane & 7) + ((lane >> 4) & 1) * 8) * 80
                                             + ((lane >> 3) & 1) * 16);

    for (int i = 0; i < NK; i++) {
        if (i == NK - 1) { CP_WAIT(0); } else { CP_WAIT(1); }
        __syncthreads();
        if (i + 2 < NK) issue(i + 2);

        const unsigned so = (unsigned)((i % NSTG) * STG_B);
        const unsigned a_base = a_base0 + so;
        const unsigned b_base = b_base0 + so;
#pragma unroll
        for (int ks = 0; ks < 2; ks++) {
            unsigned af[4][4], bf[4][2];
#pragma unroll
            for (int mt = 0; mt < 4; mt++)
                ldsm_x4(af[mt][0], af[mt][1], af[mt][2], af[mt][3],
                        a_base + (unsigned)(mt * 16 * 80 + ks * 32));
#pragma unroll
            for (int p = 0; p < 2; p++)
                ldsm_x4(bf[2 * p][0], bf[2 * p][1], bf[2 * p + 1][0], bf[2 * p + 1][1],
                        b_base + (unsigned)(p * 16 * 80 + ks * 32));
#pragma unroll
            for (int mt = 0; mt < 4; mt++)
#pragma unroll
                for (int nt = 0; nt < 4; nt++)
                    mma_f16(c[mt][nt], af[mt], bf[nt]);
        }
    }

#pragma unroll
    for (int mt = 0; mt < 4; mt++) {
#pragma unroll
        for (int nt = 0; nt < 4; nt++) {
            int row = bm + wm + mt * 16 + (lane >> 2);
            int col = bn + wn + nt * 8 + (lane & 3) * 2;
            if (OUTH) {
                __half* C16 = (__half*)Cv;
                *(__half2*)&C16[(size_t)row * 1024 + col] =
                    __floats2half2_rn(c[mt][nt][0], c[mt][nt][1]);
                *(__half2*)&C16[(size_t)(row + 8) * 1024 + col] =
                    __floats2half2_rn(c[mt][nt][2], c[mt][nt][3]);
            } else {
                float* Cf = (float*)Cv;
                *(float2*)&Cf[(size_t)row * 1024 + col] =
                    make_float2(c[mt][nt][0], c[mt][nt][1]);
                *(float2*)&Cf[(size_t)(row + 8) * 1024 + col] =
                    make_float2(c[mt][nt][2], c[mt][nt][3]);
            }
        }
    }
}

// ---------------------------------------------------------------------------
// Per-head LayerNorm over last dim S=64 on fp16 (fp32 internal math).
// ---------------------------------------------------------------------------
__global__ __launch_bounds__(256) void ln_h(__half* __restrict__ buf,
                                            const float* __restrict__ w,
                                            const float* __restrict__ b)
{
    int gw = (blockIdx.x * blockDim.x + threadIdx.x) >> 5;
    int lane = threadIdx.x & 31;
    if (gw >= BT * H) return;

    __half2* v = (__half2*)(buf + (size_t)gw * S);
    float2 x = __half22float2(v[lane]);

    float sum = x.x + x.y;
#pragma unroll
    for (int o = 16; o > 0; o >>= 1) sum += __shfl_xor_sync(0xffffffffu, sum, o);
    float mu = sum * (1.0f / 64.0f);

    float dx = x.x - mu, dy = x.y - mu;
    float vs = dx * dx + dy * dy;
#pragma unroll
    for (int o = 16; o > 0; o >>= 1) vs += __shfl_xor_sync(0xffffffffu, vs, o);
    float rs = rsqrtf(vs * (1.0f / 64.0f) + 1e-5f);

    v[lane] = __floats2half2_rn(dx * rs * w[lane * 2]     + b[lane * 2],
                                dy * rs * w[lane * 2 + 1] + b[lane * 2 + 1]);
}

// ---------------------------------------------------------------------------
// Causal flash attention, fp16 mma.sync m16n8k16.
// Block 128 threads (4 warps), 64-query tile; warp w owns rows 16w..16w+15.
// SMEM (bytes): QP[64][72h]=9216 @0; K stages 2x9216 @9216; V stages 2x9216 @27648.
// K/V double-buffered via cp.async (pure copies). P aliases QP (fp16).
// ---------------------------------------------------------------------------
#define ALD 72              // halves per row (144 B)
#define AROW 144
#define AQP_OFF 0
#define AK_OFF  9216
#define AV_OFF  27648
#define ATT_SMEM 46080

__global__ __launch_bounds__(128) void attn(const __half* __restrict__ Q,
                                            const __half* __restrict__ K,
                                            const __half* __restrict__ V,
                                            __half* __restrict__ O)
{
    extern __shared__ __align__(16) char sma[];
    const unsigned sbase = smem_u32(sma);
    __half* QP = (__half*)sma;

    const int qt = gridDim.x - 1 - blockIdx.x;   // big tiles first
    const int bh = blockIdx.y;
    const int b  = bh >> 4, h = bh & 15;
    const int tid  = threadIdx.x;
    const int lane = tid & 31;
    const int w    = tid >> 5;

    const size_t qbase = ((size_t)b * T + (size_t)qt * 64) * E + h * S;

    // stage Q (plain copies, once)
    for (int idx = tid; idx < 512; idx += 128) {
        int r = idx >> 3, c = idx & 7;
        *(uint4*)(QP + r * ALD + c * 8) = *(const uint4*)(Q + qbase + (size_t)r * E + c * 8);
    }

    auto issueKV = [&](int kt, int sb) {
        const size_t kb = ((size_t)b * T + (size_t)kt * 64) * E + h * S;
        const __half* kp = K + kb;
        const __half* vp = V + kb;
        const unsigned kd = sbase + AK_OFF + (unsigned)sb * 9216;
        const unsigned vd = sbase + AV_OFF + (unsigned)sb * 9216;
#pragma unroll
        for (int i = 0; i < 4; i++) {
            int idx = i * 128 + tid;
            int r = idx >> 3, c = idx & 7;
            CP_ASYNC16(kd + r * AROW + c * 16, kp + (size_t)r * E + c * 8);
            CP_ASYNC16(vd + r * AROW + c * 16, vp + (size_t)r * E + c * 8);
        }
        CP_COMMIT();
    };

    issueKV(0, 0);
    __syncthreads();   // Q staged

    // Q/P A-fragment base (reused for both: same buffer + stride)
    const unsigned a_base = sbase + AQP_OFF +
        (unsigned)((16 * w + (lane & 15)) * AROW + ((lane >> 4) & 1) * 16);
    unsigned Qf[4][4];
#pragma unroll
    for (int ks = 0; ks < 4; ks++)
        ldsm_x4(Qf[ks][0], Qf[ks][1], Qf[ks][2], Qf[ks][3],
                a_base + (unsigned)(ks * 32));

    // per-lane fragment offsets
    const unsigned kb_off = (unsigned)(((lane & 7) + ((lane >> 4) & 1) * 8) * AROW
                                       + ((lane >> 3) & 1) * 16);
    const unsigned vb_off = (unsigned)(((lane & 7) + ((lane >> 3) & 1) * 8) * AROW
                                       + ((lane >> 4) & 1) * 16);

    float o[8][4];
    float m[2], l[2];
#pragma unroll
    for (int nt = 0; nt < 8; nt++)
#pragma unroll
        for (int i = 0; i < 4; i++) o[nt][i] = 0.f;
    m[0] = m[1] = -1e30f;
    l[0] = l[1] = 0.f;

    const int row0 = (lane >> 2);
    const int colb = 2 * (lane & 3);

    for (int kt = 0; kt <= qt; kt++) {
        const int sb = kt & 1;
        CP_WAIT(0);
        __syncthreads();                 // K/V(kt) visible; all done with old buffers
        if (kt < qt) issueKV(kt + 1, sb ^ 1);

        const unsigned kbb = sbase + AK_OFF + (unsigned)sb * 9216 + kb_off;
        const unsigned vbb = sbase + AV_OFF + (unsigned)sb * 9216 + vb_off;

        // ---- S = Q K^T ----
        float s[8][4];
#pragma unroll
        for (int nt = 0; nt < 8; nt++)
#pragma unroll
            for (int i = 0; i < 4; i++) s[nt][i] = 0.f;

#pragma unroll
        for (int ks = 0; ks < 4; ks++) {
            unsigned bf[8][2];
#pragma unroll
            for (int p = 0; p < 4; p++)
                ldsm_x4(bf[2 * p][0], bf[2 * p][1], bf[2 * p + 1][0], bf[2 * p + 1][1],
                        kbb + (unsigned)(p * 16 * AROW + ks * 32));
#pragma unroll
            for (int nt = 0; nt < 8; nt++)
                mma_f16(s[nt], Qf[ks], bf[nt]);
        }

        // ---- online softmax ----
        const bool diag = (kt == qt);
#pragma unroll
        for (int hh = 0; hh < 2; hh++) {
            const int rloc = 16 * w + row0 + 8 * hh;
            float rmax = -1e30f;
#pragma unroll
            for (int nt = 0; nt < 8; nt++) {
#pragma unroll
                for (int e = 0; e < 2; e++) {
                    float sv = s[nt][2 * hh + e] * 0.125f;
                    if (diag && (8 * nt + colb + e > rloc)) sv = -1e30f;
                    s[nt][2 * hh + e] = sv;
                    rmax = fmaxf(rmax, sv);
                }
            }
            rmax = fmaxf(rmax, __shfl_xor_sync(0xffffffffu, rmax, 1));
            rmax = fmaxf(rmax, __shfl_xor_sync(0xffffffffu, rmax, 2));
            float mnew = fmaxf(m[hh], rmax);
            float alpha = __expf(m[hh] - mnew);
            m[hh] = mnew;
            float rsum = 0.f;
#pragma unroll
            for (int nt = 0; nt < 8; nt++) {
#pragma unroll
                for (int e = 0; e < 2; e++) {
                    float p = __expf(s[nt][2 * hh + e] - mnew);
                    s[nt][2 * hh + e] = p;
                    rsum += p;
                }
            }
            rsum += __shfl_xor_sync(0xffffffffu, rsum, 1);
            rsum += __shfl_xor_sync(0xffffffffu, rsum, 2);
            l[hh] = l[hh] * alpha + rsum;
#pragma unroll
            for (int nt = 0; nt < 8; nt++) {
                o[nt][2 * hh]     *= alpha;
                o[nt][2 * hh + 1] *= alpha;
            }
        }

        // ---- store P (fp16) into aliased QP buffer; warp-private rows ----
        __syncwarp();
#pragma unroll
        for (int nt = 0; nt < 8; nt++) {
            *(__half2*)&QP[(16 * w + row0) * ALD + 8 * nt + colb] =
                __floats2half2_rn(s[nt][0], s[nt][1]);
            *(__half2*)&QP[(16 * w + row0 + 8) * ALD + 8 * nt + colb] =
                __floats2half2_rn(s[nt][2], s[nt][3]);
        }
        __syncwarp();

        // ---- O += P V  (V B-frags via ldmatrix.trans) ----
#pragma unroll
        for (int ks = 0; ks < 4; ks++) {
            unsigned pa[4];
            ldsm_x4(pa[0], pa[1], pa[2], pa[3], a_base + (unsigned)(ks * 32));
            unsigned bv[8][2];
#pragma unroll
            for (int p = 0; p < 4; p++)
                ldsm_x4t(bv[2 * p][0], bv[2 * p][1], bv[2 * p + 1][0], bv[2 * p + 1][1],
                         vbb + (unsigned)(ks * 16 * AROW + p * 32));
#pragma unroll
            for (int nt = 0; nt < 8; nt++)
                mma_f16(o[nt], pa, bv[nt]);
        }
    }

    // ---- epilogue: fp16 O ----
    const float inv0 = 1.0f / l[0];
    const float inv1 = 1.0f / l[1];
    const size_t r0g = qbase + (size_t)(16 * w + row0) * E;
    const size_t r1g = qbase + (size_t)(16 * w + row0 + 8) * E;
#pragma unroll
    for (int nt = 0; nt < 8; nt++) {
        int col = 8 * nt + colb;
        *(__half2*)&O[r0g + col] = __floats2half2_rn(o[nt][0] * inv0, o[nt][1] * inv0);
        *(__half2*)&O[r1g + col] = __floats2half2_rn(o[nt][2] * inv1, o[nt][3] * inv1);
    }
}

// ---------------------------------------------------------------------------
extern "C" void kernel_launch(void* const* d_in, const int* in_sizes, int n_in,
                              void* d_out, int out_size)
{
    const float* x    = (const float*)d_in[0];
    const float* Wk   = (const float*)d_in[1];
    const float* Wq   = (const float*)d_in[2];
    const float* Wv   = (const float*)d_in[3];
    const float* Wu   = (const float*)d_in[4];
    const float* klnw = (const float*)d_in[5];
    const float* klnb = (const float*)d_in[6];
    const float* qlnw = (const float*)d_in[7];
    const float* qlnb = (const float*)d_in[8];
    float* out = (float*)d_out;

    __half *gx, *gq, *gk, *gv, *go, *gwq, *gwk, *gwv, *gwu;
    cudaGetSymbolAddress((void**)&gx,  g_X16);
    cudaGetSymbolAddress((void**)&gq,  g_Q16);
    cudaGetSymbolAddress((void**)&gk,  g_K16);
    cudaGetSymbolAddress((void**)&gv,  g_V16);
    cudaGetSymbolAddress((void**)&go,  g_O16);
    cudaGetSymbolAddress((void**)&gwq, g_Wq16);
    cudaGetSymbolAddress((void**)&gwk, g_Wk16);
    cudaGetSymbolAddress((void**)&gwv, g_Wv16);
    cudaGetSymbolAddress((void**)&gwu, g_Wu16);

    const int gemm_smem = 2 * NSTG * STG_B;   // 61440
    cudaFuncSetAttribute(gemm_h<1>, cudaFuncAttributeMaxDynamicSharedMemorySize, gemm_smem);
    cudaFuncSetAttribute(gemm_h<0>, cudaFuncAttributeMaxDynamicSharedMemorySize, gemm_smem);
    cudaFuncSetAttribute(attn, cudaFuncAttributeMaxDynamicSharedMemorySize, ATT_SMEM);

    // fp32 -> fp16 once
    cvt_h<<<(BT * E / 8 + 255) / 256, 256>>>(x, gx, BT * E / 8);
    cvt_h<<<(E * E / 8 + 255) / 256, 256>>>(Wq, gwq, E * E / 8);
    cvt_h<<<(E * E / 8 + 255) / 256, 256>>>(Wk, gwk, E * E / 8);
    cvt_h<<<(E * E / 8 + 255) / 256, 256>>>(Wv, gwv, E * E / 8);
    cvt_h<<<(E * E / 8 + 255) / 256, 256>>>(Wu, gwu, E * E / 8);

    dim3 gemm_grid(8, 32);   // N/128, M/128
    gemm_h<1><<<gemm_grid, 256, gemm_smem>>>(gx, gwq, gq);
    gemm_h<1><<<gemm_grid, 256, gemm_smem>>>(gx, gwk, gk);
    gemm_h<1><<<gemm_grid, 256, gemm_smem>>>(gx, gwv, gv);

    ln_h<<<8192, 256>>>(gq, qlnw, qlnb);
    ln_h<<<8192, 256>>>(gk, klnw, klnb);

    attn<<<dim3(32, 32), 128, ATT_SMEM>>>(gq, gk, gv, go);

    gemm_h<0><<<gemm_grid, 256, gemm_smem>>>(go, gwu, out);
}